// round 7
// baseline (speedup 1.0000x reference)
#include <cuda_runtime.h>
#include <cuda_bf16.h>

// GraphSAGE 6-layer: dims 128->32->32->32->32->32->16
//  - p = h@Wl computed BEFORE aggregation (linearity of mean)
//  - CSR built once per launch; aggregation = pure gather (no float atomics)
//  - R7: CSR segments padded to 8 with zero-row sentinel -> aggregate uses
//        LDG.128 for both index stream (replicated int4) and value rows
//        (8 lanes x float4 per 128B row), float4 shuffle reduction.

#define NN 100000
#define EE 3200000
#define CSRSZ (EE + 8 * NN)            // padded CSR capacity
#define SCAN_NB ((NN + 1023) / 1024)   // 98 blocks

__device__ int   g_is32;
__device__ int   g_srcc[EE];
__device__ int   g_dstc[EE];
__device__ int   g_csrc[CSRSZ];
__device__ int   g_deg[NN];
__device__ int   g_cur[NN];
__device__ int   g_off[NN + 1];
__device__ int   g_bsum[128];
__device__ int   g_boff[128];
__device__ float g_inv[NN];
__device__ float g_p [(NN + 1) * 32];  // +1: zero row (sentinel target)
__device__ float g_h0[NN * 32];
__device__ float g_h1[NN * 32];

// ---------------------------------------------------------------------------
// Detect int64 vs int32 edge buffer (reads only indices < e; in-bounds both ways).
__global__ void detect_kernel(const long long* __restrict__ ei, int n) {
    __shared__ int s_bad;
    if (threadIdx.x == 0) s_bad = 0;
    __syncthreads();
    long long v = ei[threadIdx.x];           // 128 threads, indices 0..127
    if (v < 0 || v >= (long long)n) atomicAdd(&s_bad, 1);
    __syncthreads();
    if (threadIdx.x == 0) g_is32 = (s_bad > 0) ? 1 : 0;
}

__global__ void zero_deg_kernel(int n) {
    int i = blockIdx.x * blockDim.x + threadIdx.x;
    if (i < n) g_deg[i] = 0;
}

// prefill padded CSR with the zero-row sentinel (NN)
__global__ void prefill_csr_kernel() {
    int i = blockIdx.x * blockDim.x + threadIdx.x;
    if (i < CSRSZ) g_csrc[i] = NN;
}

// zero 32 floats of the sentinel row at g_p[NN*32] (DOUT=32 layout)
__global__ void zero_prow32_kernel(float* p) {
    p[(size_t)NN * 32 + threadIdx.x] = 0.f;
}
// zero 16 floats of the sentinel row at g_p[NN*16] (DOUT=16 layout)
__global__ void zero_prow16_kernel(float* p) {
    p[(size_t)NN * 16 + threadIdx.x] = 0.f;
}

// split edge_index into int32 src/dst, count in-degree
__global__ void prep_kernel(const void* __restrict__ eiv, int e, int n) {
    int i = blockIdx.x * blockDim.x + threadIdx.x;
    if (i >= e) return;
    int s, d;
    if (g_is32) {
        const int* p = (const int*)eiv;
        s = p[i];
        d = p[e + i];
    } else {
        const long long* p = (const long long*)eiv;
        s = (int)p[i];
        d = (int)p[(size_t)e + i];
    }
    if ((unsigned)s >= (unsigned)n || (unsigned)d >= (unsigned)n) {
        g_srcc[i] = -1;
        g_dstc[i] = -1;
        return;
    }
    g_srcc[i] = s;
    g_dstc[i] = d;
    atomicAdd(&g_deg[d], 1);
}

// ---------------------------------------------------------------------------
// Hierarchical scan over PADDED degrees ((deg+7)&~7).
__global__ __launch_bounds__(1024) void scan_blocks_kernel(int n) {
    __shared__ int s_wsum[32];
    int i    = blockIdx.x * 1024 + threadIdx.x;
    int lane = threadIdx.x & 31;
    int w    = threadIdx.x >> 5;
    int v = (i < n) ? ((g_deg[i] + 7) & ~7) : 0;
    int x = v;
    #pragma unroll
    for (int o = 1; o < 32; o <<= 1) {
        int t = __shfl_up_sync(0xffffffffu, x, o);
        if (lane >= o) x += t;
    }
    if (lane == 31) s_wsum[w] = x;
    __syncthreads();
    if (w == 0) {
        int ws = s_wsum[lane];
        #pragma unroll
        for (int o = 1; o < 32; o <<= 1) {
            int t = __shfl_up_sync(0xffffffffu, ws, o);
            if (lane >= o) ws += t;
        }
        s_wsum[lane] = ws;
    }
    __syncthreads();
    int incl = x + ((w == 0) ? 0 : s_wsum[w - 1]);
    if (i < n) g_off[i] = incl - v;
    if (threadIdx.x == 1023) g_bsum[blockIdx.x] = incl;
}

__global__ void scan_bsums_kernel(int nb, int n) {
    __shared__ int s_wsum[4];
    int lane = threadIdx.x & 31;
    int w    = threadIdx.x >> 5;
    int v = (threadIdx.x < nb) ? g_bsum[threadIdx.x] : 0;
    int x = v;
    #pragma unroll
    for (int o = 1; o < 32; o <<= 1) {
        int t = __shfl_up_sync(0xffffffffu, x, o);
        if (lane >= o) x += t;
    }
    if (lane == 31) s_wsum[w] = x;
    __syncthreads();
    if (w == 0 && lane < 4) {
        int ws = s_wsum[lane];
        #pragma unroll
        for (int o = 1; o < 4; o <<= 1) {
            int t = __shfl_up_sync(0x0000000fu, ws, o);
            if (lane >= o) ws += t;
        }
        s_wsum[lane] = ws;
    }
    __syncthreads();
    int incl = x + ((w == 0) ? 0 : s_wsum[w - 1]);
    g_boff[threadIdx.x] = incl - v;
    if (threadIdx.x == 127) g_off[n] = incl;
}

__global__ __launch_bounds__(1024) void finalize_offsets_kernel(int n) {
    int i = blockIdx.x * 1024 + threadIdx.x;
    if (i < n) {
        int off = g_off[i] + g_boff[blockIdx.x];
        g_off[i] = off;
        g_cur[i] = off;
        int v = g_deg[i];
        g_inv[i] = 1.0f / (float)(v > 0 ? v : 1);
    }
}

// bucket src indices by dst
__global__ void fill_kernel(int e) {
    int i = blockIdx.x * blockDim.x + threadIdx.x;
    if (i < e) {
        int d = g_dstc[i];
        if (d < 0) return;
        int slot = atomicAdd(&g_cur[d], 1);
        if (slot >= 0 && slot < CSRSZ) g_csrc[slot] = g_srcc[i];
    }
}

// ---------------------------------------------------------------------------
// Fused dual GEMM: p = relu?(h) @ Wl ; out = relu?(h) @ Wr + bl
template <int DIN, int DOUT, bool RELU_IN>
__global__ __launch_bounds__(256) void gemm_fused(
    const float* __restrict__ h,
    const float* __restrict__ Wl, const float* __restrict__ Wr,
    const float* __restrict__ bl,
    float* __restrict__ p, float* __restrict__ out, int n)
{
    constexpr int NPW = 32 / DOUT;   // nodes per warp
    __shared__ float sWl[DIN * DOUT];
    __shared__ float sWr[DIN * DOUT];
    __shared__ float sb[DOUT];
    for (int i = threadIdx.x; i < DIN * DOUT; i += blockDim.x) {
        sWl[i] = Wl[i];
        sWr[i] = Wr[i];
    }
    if (threadIdx.x < DOUT) sb[threadIdx.x] = bl[threadIdx.x];
    __syncthreads();

    int lane  = threadIdx.x & 31;
    int gwarp = (blockIdx.x * blockDim.x + threadIdx.x) >> 5;
    int sub   = lane / DOUT;
    int l     = lane % DOUT;
    int node  = gwarp * NPW + sub;
    if (node >= n) return;

    const float4* hrow = reinterpret_cast<const float4*>(h) + (size_t)node * (DIN / 4);
    float al = 0.f, ar = 0.f;
    #pragma unroll
    for (int k4 = 0; k4 < DIN / 4; k4++) {
        float4 hv = __ldg(&hrow[k4]);
        if (RELU_IN) {
            hv.x = fmaxf(hv.x, 0.f); hv.y = fmaxf(hv.y, 0.f);
            hv.z = fmaxf(hv.z, 0.f); hv.w = fmaxf(hv.w, 0.f);
        }
        int k = 4 * k4;
        al = fmaf(hv.x, sWl[(k + 0) * DOUT + l], al);
        ar = fmaf(hv.x, sWr[(k + 0) * DOUT + l], ar);
        al = fmaf(hv.y, sWl[(k + 1) * DOUT + l], al);
        ar = fmaf(hv.y, sWr[(k + 1) * DOUT + l], ar);
        al = fmaf(hv.z, sWl[(k + 2) * DOUT + l], al);
        ar = fmaf(hv.z, sWr[(k + 2) * DOUT + l], ar);
        al = fmaf(hv.w, sWl[(k + 3) * DOUT + l], al);
        ar = fmaf(hv.w, sWr[(k + 3) * DOUT + l], ar);
    }
    p  [(size_t)node * DOUT + l] = al;
    out[(size_t)node * DOUT + l] = ar + sb[l];
}

// ---------------------------------------------------------------------------
__device__ __forceinline__ int sel4(const int4& v, int r) {
    return (r == 0) ? v.x : (r == 1) ? v.y : (r == 2) ? v.z : v.w;
}

// out[node] += inv_deg[node] * sum_{j in N(node)} p[j]
// Warp per node. LPR lanes per row (float4/lane), 8 edges per loop body.
// CSR segments are padded to 8 with sentinel NN -> p's zero row; no tails.
template <int DOUT>
__global__ __launch_bounds__(256) void aggregate_kernel(
    const float* __restrict__ p, float* __restrict__ out, int n)
{
    constexpr int LPR = DOUT / 4;    // 8 (DOUT=32) or 4 (DOUT=16)
    int lane = threadIdx.x & 31;
    int node = (blockIdx.x * blockDim.x + threadIdx.x) >> 5;
    if (node >= n) return;

    int beg = g_off[node];
    int pad = g_off[node + 1] - beg;           // multiple of 8
    int r   = lane / LPR;
    int col = lane % LPR;
    const float4* p4 = reinterpret_cast<const float4*>(p);

    float4 acc = make_float4(0.f, 0.f, 0.f, 0.f);
    for (int k = 0; k < pad; k += 8) {
        int4 iv0 = __ldg(reinterpret_cast<const int4*>(g_csrc + beg + k));
        int4 iv1 = __ldg(reinterpret_cast<const int4*>(g_csrc + beg + k + 4));
        if (LPR == 8) {
            // r in 0..3: edges k+r (iv0) and k+4+r (iv1)
            int s0 = sel4(iv0, r);
            int s1 = sel4(iv1, r);
            float4 v0 = __ldg(&p4[(size_t)s0 * 8 + col]);
            float4 v1 = __ldg(&p4[(size_t)s1 * 8 + col]);
            acc.x += v0.x; acc.y += v0.y; acc.z += v0.z; acc.w += v0.w;
            acc.x += v1.x; acc.y += v1.y; acc.z += v1.z; acc.w += v1.w;
        } else {
            // r in 0..7: edge k+r
            int s = (r < 4) ? sel4(iv0, r) : sel4(iv1, r - 4);
            float4 v = __ldg(&p4[(size_t)s * 4 + col]);
            acc.x += v.x; acc.y += v.y; acc.z += v.z; acc.w += v.w;
        }
    }
    // reduce across row-groups (lanes differing above LPR bits)
    #pragma unroll
    for (int o = LPR; o < 32; o <<= 1) {
        acc.x += __shfl_xor_sync(0xffffffffu, acc.x, o);
        acc.y += __shfl_xor_sync(0xffffffffu, acc.y, o);
        acc.z += __shfl_xor_sync(0xffffffffu, acc.z, o);
        acc.w += __shfl_xor_sync(0xffffffffu, acc.w, o);
    }
    if (lane < LPR) {
        float inv = g_inv[node];
        float4* o4 = reinterpret_cast<float4*>(out) + (size_t)node * LPR + lane;
        float4 cur = *o4;
        cur.x += acc.x * inv; cur.y += acc.y * inv;
        cur.z += acc.z * inv; cur.w += acc.w * inv;
        *o4 = cur;
    }
}

// ---------------------------------------------------------------------------
extern "C" void kernel_launch(void* const* d_in, const int* in_sizes, int n_in,
                              void* d_out, int out_size)
{
    const float* x  = (const float*)d_in[0];
    const void*  ei = d_in[1];
    const float *Wl[6], *bl[6], *Wr[6];
    for (int i = 0; i < 6; i++) {
        Wl[i] = (const float*)d_in[2 + 3 * i];
        bl[i] = (const float*)d_in[3 + 3 * i];
        Wr[i] = (const float*)d_in[4 + 3 * i];
    }
    float* out = (float*)d_out;
    const int n = NN, e = EE;

    float *pp = nullptr, *ph0 = nullptr, *ph1 = nullptr;
    cudaGetSymbolAddress((void**)&pp,  g_p);
    cudaGetSymbolAddress((void**)&ph0, g_h0);
    cudaGetSymbolAddress((void**)&ph1, g_h1);

    // ---- CSR build (once per launch) ----
    detect_kernel<<<1, 128>>>((const long long*)ei, n);
    zero_deg_kernel<<<(n + 255) / 256, 256>>>(n);
    prefill_csr_kernel<<<(CSRSZ + 511) / 512, 512>>>();
    zero_prow32_kernel<<<1, 32>>>(pp);
    prep_kernel<<<(e + 255) / 256, 256>>>(ei, e, n);
    scan_blocks_kernel<<<SCAN_NB, 1024>>>(n);
    scan_bsums_kernel<<<1, 128>>>(SCAN_NB, n);
    finalize_offsets_kernel<<<SCAN_NB, 1024>>>(n);
    fill_kernel<<<(e + 255) / 256, 256>>>(e);

    const int blocksG32 = (n * 32 + 255) / 256;             // gemm DOUT=32
    const int blocksG16 = (((n + 1) / 2) * 32 + 255) / 256; // gemm DOUT=16 (NPW=2)
    const int blocksA   = (n * 32 + 255) / 256;             // aggregate: warp/node

    // layer 0: x(128) -> h0(32)
    gemm_fused<128, 32, false><<<blocksG32, 256>>>(x, Wl[0], Wr[0], bl[0], pp, ph0, n);
    aggregate_kernel<32><<<blocksA, 256>>>(pp, ph0, n);
    // layer 1
    gemm_fused<32, 32, true><<<blocksG32, 256>>>(ph0, Wl[1], Wr[1], bl[1], pp, ph1, n);
    aggregate_kernel<32><<<blocksA, 256>>>(pp, ph1, n);
    // layer 2
    gemm_fused<32, 32, true><<<blocksG32, 256>>>(ph1, Wl[2], Wr[2], bl[2], pp, ph0, n);
    aggregate_kernel<32><<<blocksA, 256>>>(pp, ph0, n);
    // layer 3
    gemm_fused<32, 32, true><<<blocksG32, 256>>>(ph0, Wl[3], Wr[3], bl[3], pp, ph1, n);
    aggregate_kernel<32><<<blocksA, 256>>>(pp, ph1, n);
    // layer 4
    gemm_fused<32, 32, true><<<blocksG32, 256>>>(ph1, Wl[4], Wr[4], bl[4], pp, ph0, n);
    aggregate_kernel<32><<<blocksA, 256>>>(pp, ph0, n);
    // layer 5: h0 -> d_out (16)
    gemm_fused<32, 16, true><<<blocksG16, 256>>>(ph0, Wl[5], Wr[5], bl[5], pp, out, n);
    zero_prow16_kernel<<<1, 16>>>(pp);   // sentinel row for DOUT=16 layout
    aggregate_kernel<16><<<blocksA, 256>>>(pp, out, n);
}

// round 8
// speedup vs baseline: 1.0876x; 1.0876x over previous
#include <cuda_runtime.h>
#include <cuda_fp16.h>

// GraphSAGE 6-layer: dims 128->32->32->32->32->32->16
//  R8: p stored fp16 (halves aggregate L2 traffic);
//      GEMM uses packed fma.rn.f32x2 (Wl/Wr paths together), W pre-packed in
//      smem, h duplicated {v,v} in smem, 4 nodes/warp (4x W-LDS reuse);
//      CSR prefill replaced by pad-tails; gemm0 placed 4th for ncu.

#define NN 100000
#define EE 3200000
#define CSRSZ (EE + 8 * NN)
#define SCAN_NB ((NN + 1023) / 1024)   // 98 blocks

__device__ int    g_is32;
__device__ int    g_srcc[EE];
__device__ int    g_dstc[EE];
__device__ int    g_csrc[CSRSZ];
__device__ int    g_deg[NN];
__device__ int    g_cur[NN];
__device__ int    g_off[NN + 1];
__device__ int    g_bsum[128];
__device__ int    g_boff[128];
__device__ float  g_inv[NN];
__device__ __half g_p [(NN + 1) * 32];   // fp16 messages; row NN = zero sentinel
__device__ float  g_h0[NN * 32];
__device__ float  g_h1[NN * 32];

// ---------------------------------------------------------------------------
// packed f32x2 helpers (sm_100+)
__device__ __forceinline__ unsigned long long fma_f32x2(
    unsigned long long a, unsigned long long b, unsigned long long c) {
    unsigned long long d;
    asm("fma.rn.f32x2 %0, %1, %2, %3;" : "=l"(d) : "l"(a), "l"(b), "l"(c));
    return d;
}
__device__ __forceinline__ unsigned long long pack_f32(float lo, float hi) {
    unsigned long long r;
    asm("mov.b64 %0, {%1, %2};" : "=l"(r) : "f"(lo), "f"(hi));
    return r;
}
__device__ __forceinline__ unsigned long long dup_f32(float v) {
    unsigned long long r;
    asm("mov.b64 %0, {%1, %1};" : "=l"(r) : "f"(v));
    return r;
}
__device__ __forceinline__ float2 unpack_f32x2(unsigned long long v) {
    float2 r;
    asm("mov.b64 {%0, %1}, %2;" : "=f"(r.x), "=f"(r.y) : "l"(v));
    return r;
}
__device__ __forceinline__ int sel4(const int4& v, int r) {
    return (r == 0) ? v.x : (r == 1) ? v.y : (r == 2) ? v.z : v.w;
}

// ---------------------------------------------------------------------------
// Detect int64 vs int32 edge buffer (reads only indices < e; in-bounds both ways).
__global__ void detect_kernel(const long long* __restrict__ ei, int n) {
    __shared__ int s_bad;
    if (threadIdx.x == 0) s_bad = 0;
    __syncthreads();
    long long v = ei[threadIdx.x];
    if (v < 0 || v >= (long long)n) atomicAdd(&s_bad, 1);
    __syncthreads();
    if (threadIdx.x == 0) g_is32 = (s_bad > 0) ? 1 : 0;
}

__global__ void zero_deg_kernel(int n) {
    int i = blockIdx.x * blockDim.x + threadIdx.x;
    if (i < n) g_deg[i] = 0;
}

// split edge_index into int32 src/dst, count in-degree
__global__ void prep_kernel(const void* __restrict__ eiv, int e, int n) {
    int i = blockIdx.x * blockDim.x + threadIdx.x;
    if (i >= e) return;
    int s, d;
    if (g_is32) {
        const int* p = (const int*)eiv;
        s = p[i];
        d = p[e + i];
    } else {
        const long long* p = (const long long*)eiv;
        s = (int)p[i];
        d = (int)p[(size_t)e + i];
    }
    if ((unsigned)s >= (unsigned)n || (unsigned)d >= (unsigned)n) {
        g_srcc[i] = -1;
        g_dstc[i] = -1;
        return;
    }
    g_srcc[i] = s;
    g_dstc[i] = d;
    atomicAdd(&g_deg[d], 1);
}

// ---------------------------------------------------------------------------
// Hierarchical scan over PADDED degrees ((deg+7)&~7).
__global__ __launch_bounds__(1024) void scan_blocks_kernel(int n) {
    __shared__ int s_wsum[32];
    int i    = blockIdx.x * 1024 + threadIdx.x;
    int lane = threadIdx.x & 31;
    int w    = threadIdx.x >> 5;
    int v = (i < n) ? ((g_deg[i] + 7) & ~7) : 0;
    int x = v;
    #pragma unroll
    for (int o = 1; o < 32; o <<= 1) {
        int t = __shfl_up_sync(0xffffffffu, x, o);
        if (lane >= o) x += t;
    }
    if (lane == 31) s_wsum[w] = x;
    __syncthreads();
    if (w == 0) {
        int ws = s_wsum[lane];
        #pragma unroll
        for (int o = 1; o < 32; o <<= 1) {
            int t = __shfl_up_sync(0xffffffffu, ws, o);
            if (lane >= o) ws += t;
        }
        s_wsum[lane] = ws;
    }
    __syncthreads();
    int incl = x + ((w == 0) ? 0 : s_wsum[w - 1]);
    if (i < n) g_off[i] = incl - v;
    if (threadIdx.x == 1023) g_bsum[blockIdx.x] = incl;
}

__global__ void scan_bsums_kernel(int nb, int n) {
    __shared__ int s_wsum[4];
    int lane = threadIdx.x & 31;
    int w    = threadIdx.x >> 5;
    int v = (threadIdx.x < nb) ? g_bsum[threadIdx.x] : 0;
    int x = v;
    #pragma unroll
    for (int o = 1; o < 32; o <<= 1) {
        int t = __shfl_up_sync(0xffffffffu, x, o);
        if (lane >= o) x += t;
    }
    if (lane == 31) s_wsum[w] = x;
    __syncthreads();
    if (w == 0 && lane < 4) {
        int ws = s_wsum[lane];
        #pragma unroll
        for (int o = 1; o < 4; o <<= 1) {
            int t = __shfl_up_sync(0x0000000fu, ws, o);
            if (lane >= o) ws += t;
        }
        s_wsum[lane] = ws;
    }
    __syncthreads();
    int incl = x + ((w == 0) ? 0 : s_wsum[w - 1]);
    g_boff[threadIdx.x] = incl - v;
    if (threadIdx.x == 127) g_off[n] = incl;
}

__global__ __launch_bounds__(1024) void finalize_offsets_kernel(int n) {
    int i = blockIdx.x * 1024 + threadIdx.x;
    if (i < n) {
        int off = g_off[i] + g_boff[blockIdx.x];
        g_off[i] = off;
        g_cur[i] = off;
        int v = g_deg[i];
        g_inv[i] = 1.0f / (float)(v > 0 ? v : 1);
    }
}

// bucket src indices by dst
__global__ void fill_kernel(int e) {
    int i = blockIdx.x * blockDim.x + threadIdx.x;
    if (i < e) {
        int d = g_dstc[i];
        if (d < 0) return;
        int slot = atomicAdd(&g_cur[d], 1);
        if (slot >= 0 && slot < CSRSZ) g_csrc[slot] = g_srcc[i];
    }
}

// write sentinel into pad gaps [cur[i], off[i+1]); also zero the DOUT=32 sentinel row
__global__ void pad_tails_kernel(__half* p16, int n) {
    int i = blockIdx.x * blockDim.x + threadIdx.x;
    if (i < n) {
        int end = g_off[i + 1];
        for (int j = g_cur[i]; j < end; j++)
            if (j >= 0 && j < CSRSZ) g_csrc[j] = NN;
    }
    if (blockIdx.x == 0 && threadIdx.x < 32)
        p16[(size_t)NN * 32 + threadIdx.x] = __float2half(0.f);
}

// zero the DOUT=16-layout sentinel row (needed after gemm5 overwrote that region)
__global__ void zero_prow16_kernel(__half* p16) {
    p16[(size_t)NN * 16 + threadIdx.x] = __float2half(0.f);
}

// ---------------------------------------------------------------------------
// Fused dual GEMM via packed f32x2: {p, out} = relu?(h) @ {Wl, Wr} (+bl on out).
// 8 warps/block; each warp handles 4*NG consecutive nodes (NG = 32/DOUT).
// smem: W pre-packed {Wl,Wr} as b64; h rows duplicated {v,v} as b64.
template <int DIN, int DOUT, bool RELU_IN>
__global__ __launch_bounds__(256) void gemm_fused(
    const float* __restrict__ h,
    const float* __restrict__ Wl, const float* __restrict__ Wr,
    const float* __restrict__ bl,
    __half* __restrict__ p, float* __restrict__ out, int n)
{
    constexpr int NG  = 32 / DOUT;    // lane groups per warp (1 or 2)
    constexpr int NPW = 4 * NG;       // nodes per warp
    constexpr int NPB = 8 * NPW;      // nodes per block
    extern __shared__ unsigned long long smem_u[];
    unsigned long long* sW = smem_u;                     // DIN*DOUT
    unsigned long long* sh = smem_u + DIN * DOUT;        // 8*NPW*DIN
    float* sb = (float*)(sh + 8 * NPW * DIN);            // DOUT

    for (int i = threadIdx.x; i < DIN * DOUT; i += 256)
        sW[i] = pack_f32(Wl[i], Wr[i]);
    if (threadIdx.x < DOUT) sb[threadIdx.x] = bl[threadIdx.x];

    int w     = threadIdx.x >> 5;
    int lane  = threadIdx.x & 31;
    int wbase = blockIdx.x * NPB + w * NPW;

    // stage NPW h rows, duplicated {v,v}, relu applied, zero-fill out of range
    {
        constexpr int LIM = NPW * DIN;
        const float* hb = h + (size_t)wbase * DIN;
        long rem = (long)n - (long)wbase;
        int vmax = (rem <= 0) ? 0 : (rem * (long)DIN < LIM ? (int)(rem * DIN) : LIM);
        unsigned long long* shw = sh + w * LIM;
        for (int idx = lane; idx < LIM; idx += 32) {
            float v = (idx < vmax) ? hb[idx] : 0.f;
            if (RELU_IN) v = fmaxf(v, 0.f);
            shw[idx] = dup_f32(v);
        }
    }
    __syncthreads();

    int grp = lane / DOUT;    // 0..NG-1
    int col = lane % DOUT;
    const unsigned long long* mysh = sh + w * NPW * DIN;

    unsigned long long acc[4];
    #pragma unroll
    for (int j = 0; j < 4; j++) acc[j] = 0ull;

    for (int k = 0; k < DIN; k += 2) {
        unsigned long long w0 = sW[k * DOUT + col];
        unsigned long long w1 = sW[(k + 1) * DOUT + col];
        #pragma unroll
        for (int j = 0; j < 4; j++) {
            const ulonglong2 hd = *reinterpret_cast<const ulonglong2*>(
                mysh + (j * NG + grp) * DIN + k);
            acc[j] = fma_f32x2(hd.x, w0, acc[j]);
            acc[j] = fma_f32x2(hd.y, w1, acc[j]);
        }
    }

    float bias = sb[col];
    #pragma unroll
    for (int j = 0; j < 4; j++) {
        int node = wbase + j * NG + grp;
        if (node < n) {
            float2 v = unpack_f32x2(acc[j]);
            p  [(size_t)node * DOUT + col] = __float2half_rn(v.x);
            out[(size_t)node * DOUT + col] = v.y + bias;
        }
    }
}

// ---------------------------------------------------------------------------
// out[node] += inv_deg[node] * mean-sum of fp16 p rows (64B or 32B each).
// Warp per node; 8 edges per iter; 4 lanes per row chunk; pad via sentinel->zero row.
template <int DOUT>
__global__ __launch_bounds__(256) void aggregate_kernel(
    const __half* __restrict__ p, float* __restrict__ out, int n)
{
    constexpr int HPL = DOUT / 4;          // halves per lane: 8 or 4
    int lane = threadIdx.x & 31;
    int node = (blockIdx.x * blockDim.x + threadIdx.x) >> 5;
    if (node >= n) return;

    int beg = g_off[node];
    int pad = g_off[node + 1] - beg;       // multiple of 8
    int r = lane >> 2;                     // 0..7 edge slot
    int c = lane & 3;                      // row chunk

    float f[HPL];
    #pragma unroll
    for (int q = 0; q < HPL; q++) f[q] = 0.f;

    for (int k = 0; k < pad; k += 8) {
        int4 iv0 = __ldg(reinterpret_cast<const int4*>(g_csrc + beg + k));
        int4 iv1 = __ldg(reinterpret_cast<const int4*>(g_csrc + beg + k + 4));
        int s = (r < 4) ? sel4(iv0, r) : sel4(iv1, r - 4);
        if (DOUT == 32) {
            uint4 v = __ldg(reinterpret_cast<const uint4*>(p + (size_t)s * 32) + c);
            const __half2* h2 = reinterpret_cast<const __half2*>(&v);
            #pragma unroll
            for (int q = 0; q < 4; q++) {
                float2 fv = __half22float2(h2[q]);
                f[2 * q]     += fv.x;
                f[2 * q + 1] += fv.y;
            }
        } else {
            uint2 v = __ldg(reinterpret_cast<const uint2*>(p + (size_t)s * 16) + c);
            const __half2* h2 = reinterpret_cast<const __half2*>(&v);
            #pragma unroll
            for (int q = 0; q < 2; q++) {
                float2 fv = __half22float2(h2[q]);
                f[2 * q]     += fv.x;
                f[2 * q + 1] += fv.y;
            }
        }
    }
    #pragma unroll
    for (int o = 4; o < 32; o <<= 1) {
        #pragma unroll
        for (int q = 0; q < HPL; q++)
            f[q] += __shfl_xor_sync(0xffffffffu, f[q], o);
    }
    if (lane < 4) {
        float inv = g_inv[node];
        float* ob = out + (size_t)node * DOUT + lane * HPL;
        if (DOUT == 32) {
            float4* o4 = reinterpret_cast<float4*>(ob);
            float4 a = o4[0], b = o4[1];
            a.x += f[0] * inv; a.y += f[1] * inv; a.z += f[2] * inv; a.w += f[3] * inv;
            b.x += f[4] * inv; b.y += f[5] * inv; b.z += f[6] * inv; b.w += f[7] * inv;
            o4[0] = a; o4[1] = b;
        } else {
            float4* o4 = reinterpret_cast<float4*>(ob);
            float4 a = o4[0];
            a.x += f[0] * inv; a.y += f[1] * inv; a.z += f[2] * inv; a.w += f[3] * inv;
            o4[0] = a;
        }
    }
}

// ---------------------------------------------------------------------------
extern "C" void kernel_launch(void* const* d_in, const int* in_sizes, int n_in,
                              void* d_out, int out_size)
{
    const float* x  = (const float*)d_in[0];
    const void*  ei = d_in[1];
    const float *Wl[6], *bl[6], *Wr[6];
    for (int i = 0; i < 6; i++) {
        Wl[i] = (const float*)d_in[2 + 3 * i];
        bl[i] = (const float*)d_in[3 + 3 * i];
        Wr[i] = (const float*)d_in[4 + 3 * i];
    }
    float* out = (float*)d_out;
    const int n = NN, e = EE;

    __half* pp = nullptr;
    float *ph0 = nullptr, *ph1 = nullptr;
    cudaGetSymbolAddress((void**)&pp,  g_p);
    cudaGetSymbolAddress((void**)&ph0, g_h0);
    cudaGetSymbolAddress((void**)&ph1, g_h1);

    // dynamic smem sizes per gemm instantiation
    const int SM_L0 = (128 * 32 + 8 * 4 * 128) * 8 + 32 * 4;  // 65664
    const int SM_LS = (32 * 32 + 8 * 4 * 32) * 8 + 32 * 4;    // 16512
    const int SM_L5 = (32 * 16 + 8 * 8 * 32) * 8 + 16 * 4;    // 20544
    cudaFuncSetAttribute(gemm_fused<128, 32, false>,
                         cudaFuncAttributeMaxDynamicSharedMemorySize, SM_L0);
    cudaFuncSetAttribute(gemm_fused<32, 32, true>,
                         cudaFuncAttributeMaxDynamicSharedMemorySize, SM_LS);
    cudaFuncSetAttribute(gemm_fused<32, 16, true>,
                         cudaFuncAttributeMaxDynamicSharedMemorySize, SM_L5);

    const int G32 = (n + 31) / 32;     // 3125 blocks (32 nodes/block)
    const int G16 = (n + 63) / 64;     // 1563 blocks (64 nodes/block)
    const int blocksA = (n * 32 + 255) / 256;

    // ---- launch sequence (gemm0 placed 4th for ncu attribution) ----
    zero_deg_kernel<<<(n + 255) / 256, 256>>>(n);
    detect_kernel<<<1, 128>>>((const long long*)ei, n);
    prep_kernel<<<(e + 255) / 256, 256>>>(ei, e, n);
    gemm_fused<128, 32, false><<<G32, 256, SM_L0>>>(x, Wl[0], Wr[0], bl[0], pp, ph0, n);
    scan_blocks_kernel<<<SCAN_NB, 1024>>>(n);
    scan_bsums_kernel<<<1, 128>>>(SCAN_NB, n);
    finalize_offsets_kernel<<<SCAN_NB, 1024>>>(n);
    fill_kernel<<<(e + 255) / 256, 256>>>(e);
    pad_tails_kernel<<<(n + 255) / 256, 256>>>(pp, n);

    aggregate_kernel<32><<<blocksA, 256>>>(pp, ph0, n);
    gemm_fused<32, 32, true><<<G32, 256, SM_LS>>>(ph0, Wl[1], Wr[1], bl[1], pp, ph1, n);
    aggregate_kernel<32><<<blocksA, 256>>>(pp, ph1, n);
    gemm_fused<32, 32, true><<<G32, 256, SM_LS>>>(ph1, Wl[2], Wr[2], bl[2], pp, ph0, n);
    aggregate_kernel<32><<<blocksA, 256>>>(pp, ph0, n);
    gemm_fused<32, 32, true><<<G32, 256, SM_LS>>>(ph0, Wl[3], Wr[3], bl[3], pp, ph1, n);
    aggregate_kernel<32><<<blocksA, 256>>>(pp, ph1, n);
    gemm_fused<32, 32, true><<<G32, 256, SM_LS>>>(ph1, Wl[4], Wr[4], bl[4], pp, ph0, n);
    aggregate_kernel<32><<<blocksA, 256>>>(pp, ph0, n);
    gemm_fused<32, 16, true><<<G16, 256, SM_L5>>>(ph0, Wl[5], Wr[5], bl[5], pp, out, n);
    zero_prow16_kernel<<<1, 16>>>(pp);
    aggregate_kernel<16><<<blocksA, 256>>>(pp, out, n);
}

// round 10
// speedup vs baseline: 1.2231x; 1.1245x over previous
#include <cuda_runtime.h>
#include <cuda_fp16.h>

// GraphSAGE 6-layer: dims 128->32->32->32->32->32->16
//  R10: R9 GEMM (h in registers + shuffle broadcast, W smem packed by k-pairs,
//       FFMA2) with the lane<->k-pair mapping generalized so DIN=32 layers
//       compile: KPL = max(1, NKP/WIDTH), SRC_CNT = NKP/KPL, lanes hold
//       redundant copies when NKP < WIDTH.
//       Aggregation (fp16 p) and CSR build unchanged from R8.

#define NN 100000
#define EE 3200000
#define CSRSZ (EE + 8 * NN)
#define SCAN_NB ((NN + 1023) / 1024)   // 98 blocks

__device__ int    g_is32;
__device__ int    g_srcc[EE];
__device__ int    g_dstc[EE];
__device__ int    g_csrc[CSRSZ];
__device__ int    g_deg[NN];
__device__ int    g_cur[NN];
__device__ int    g_off[NN + 1];
__device__ int    g_bsum[128];
__device__ int    g_boff[128];
__device__ float  g_inv[NN];
__device__ __half g_p [(NN + 1) * 32];   // fp16 messages; row NN = zero sentinel
__device__ float  g_h0[NN * 32];
__device__ float  g_h1[NN * 32];

// ---------------------------------------------------------------------------
// packed f32x2 helpers (sm_100+)
__device__ __forceinline__ unsigned long long fma_f32x2(
    unsigned long long a, unsigned long long b, unsigned long long c) {
    unsigned long long d;
    asm("fma.rn.f32x2 %0, %1, %2, %3;" : "=l"(d) : "l"(a), "l"(b), "l"(c));
    return d;
}
__device__ __forceinline__ unsigned long long pack_f32(float lo, float hi) {
    unsigned long long r;
    asm("mov.b64 %0, {%1, %2};" : "=l"(r) : "f"(lo), "f"(hi));
    return r;
}
__device__ __forceinline__ float2 unpack_f32x2(unsigned long long v) {
    float2 r;
    asm("mov.b64 {%0, %1}, %2;" : "=f"(r.x), "=f"(r.y) : "l"(v));
    return r;
}
__device__ __forceinline__ int sel4(const int4& v, int r) {
    return (r == 0) ? v.x : (r == 1) ? v.y : (r == 2) ? v.z : v.w;
}

// ---------------------------------------------------------------------------
__global__ void detect_kernel(const long long* __restrict__ ei, int n) {
    __shared__ int s_bad;
    if (threadIdx.x == 0) s_bad = 0;
    __syncthreads();
    long long v = ei[threadIdx.x];
    if (v < 0 || v >= (long long)n) atomicAdd(&s_bad, 1);
    __syncthreads();
    if (threadIdx.x == 0) g_is32 = (s_bad > 0) ? 1 : 0;
}

__global__ void zero_deg_kernel(int n) {
    int i = blockIdx.x * blockDim.x + threadIdx.x;
    if (i < n) g_deg[i] = 0;
}

__global__ void prep_kernel(const void* __restrict__ eiv, int e, int n) {
    int i = blockIdx.x * blockDim.x + threadIdx.x;
    if (i >= e) return;
    int s, d;
    if (g_is32) {
        const int* p = (const int*)eiv;
        s = p[i];
        d = p[e + i];
    } else {
        const long long* p = (const long long*)eiv;
        s = (int)p[i];
        d = (int)p[(size_t)e + i];
    }
    if ((unsigned)s >= (unsigned)n || (unsigned)d >= (unsigned)n) {
        g_srcc[i] = -1;
        g_dstc[i] = -1;
        return;
    }
    g_srcc[i] = s;
    g_dstc[i] = d;
    atomicAdd(&g_deg[d], 1);
}

// Hierarchical scan over PADDED degrees ((deg+7)&~7).
__global__ __launch_bounds__(1024) void scan_blocks_kernel(int n) {
    __shared__ int s_wsum[32];
    int i    = blockIdx.x * 1024 + threadIdx.x;
    int lane = threadIdx.x & 31;
    int w    = threadIdx.x >> 5;
    int v = (i < n) ? ((g_deg[i] + 7) & ~7) : 0;
    int x = v;
    #pragma unroll
    for (int o = 1; o < 32; o <<= 1) {
        int t = __shfl_up_sync(0xffffffffu, x, o);
        if (lane >= o) x += t;
    }
    if (lane == 31) s_wsum[w] = x;
    __syncthreads();
    if (w == 0) {
        int ws = s_wsum[lane];
        #pragma unroll
        for (int o = 1; o < 32; o <<= 1) {
            int t = __shfl_up_sync(0xffffffffu, ws, o);
            if (lane >= o) ws += t;
        }
        s_wsum[lane] = ws;
    }
    __syncthreads();
    int incl = x + ((w == 0) ? 0 : s_wsum[w - 1]);
    if (i < n) g_off[i] = incl - v;
    if (threadIdx.x == 1023) g_bsum[blockIdx.x] = incl;
}

__global__ void scan_bsums_kernel(int nb, int n) {
    __shared__ int s_wsum[4];
    int lane = threadIdx.x & 31;
    int w    = threadIdx.x >> 5;
    int v = (threadIdx.x < nb) ? g_bsum[threadIdx.x] : 0;
    int x = v;
    #pragma unroll
    for (int o = 1; o < 32; o <<= 1) {
        int t = __shfl_up_sync(0xffffffffu, x, o);
        if (lane >= o) x += t;
    }
    if (lane == 31) s_wsum[w] = x;
    __syncthreads();
    if (w == 0 && lane < 4) {
        int ws = s_wsum[lane];
        #pragma unroll
        for (int o = 1; o < 4; o <<= 1) {
            int t = __shfl_up_sync(0x0000000fu, ws, o);
            if (lane >= o) ws += t;
        }
        s_wsum[lane] = ws;
    }
    __syncthreads();
    int incl = x + ((w == 0) ? 0 : s_wsum[w - 1]);
    g_boff[threadIdx.x] = incl - v;
    if (threadIdx.x == 127) g_off[n] = incl;
}

__global__ __launch_bounds__(1024) void finalize_offsets_kernel(int n) {
    int i = blockIdx.x * 1024 + threadIdx.x;
    if (i < n) {
        int off = g_off[i] + g_boff[blockIdx.x];
        g_off[i] = off;
        g_cur[i] = off;
        int v = g_deg[i];
        g_inv[i] = 1.0f / (float)(v > 0 ? v : 1);
    }
}

__global__ void fill_kernel(int e) {
    int i = blockIdx.x * blockDim.x + threadIdx.x;
    if (i < e) {
        int d = g_dstc[i];
        if (d < 0) return;
        int slot = atomicAdd(&g_cur[d], 1);
        if (slot >= 0 && slot < CSRSZ) g_csrc[slot] = g_srcc[i];
    }
}

// write sentinel into pad gaps; zero the DOUT=32 sentinel row
__global__ void pad_tails_kernel(__half* p16, int n) {
    int i = blockIdx.x * blockDim.x + threadIdx.x;
    if (i < n) {
        int end = g_off[i + 1];
        for (int j = g_cur[i]; j < end; j++)
            if (j >= 0 && j < CSRSZ) g_csrc[j] = NN;
    }
    if (blockIdx.x == 0 && threadIdx.x < 32)
        p16[(size_t)NN * 32 + threadIdx.x] = __float2half(0.f);
}

__global__ void zero_prow16_kernel(__half* p16) {
    p16[(size_t)NN * 16 + threadIdx.x] = __float2half(0.f);
}

// ---------------------------------------------------------------------------
// Fused dual GEMM: p = fp16(relu?(h) @ Wl); out = relu?(h) @ Wr + bl.
// h in registers as packed k-pairs, broadcast via shuffle; W in smem by k-pairs.
// KPL = k-pairs per lane (>=1); SRC_CNT = shuffle source count; lanes hold
// redundant copies when NKP < WIDTH (small DIN layers).
template <int DIN, int DOUT, bool RELU_IN, int NJ>
__global__ __launch_bounds__(256) void gemm_fused(
    const float* __restrict__ h,
    const float* __restrict__ Wl, const float* __restrict__ Wr,
    const float* __restrict__ bl,
    __half* __restrict__ p, float* __restrict__ out, int n)
{
    constexpr int NG      = 32 / DOUT;              // 1 or 2 lane groups
    constexpr int WIDTH   = 32 / NG;                // shuffle width: 32 or 16
    constexpr int NKP     = DIN / 2;                // total k-pairs
    constexpr int KPL     = (NKP >= WIDTH) ? (NKP / WIDTH) : 1;  // k-pairs/lane
    constexpr int SRC_CNT = NKP / KPL;              // shuffle sources (<= WIDTH)
    constexpr int NPW     = NJ * NG;                // nodes per warp
    constexpr int NPB     = 8 * NPW;                // nodes per block

    __shared__ unsigned long long sWl2[NKP * DOUT];
    __shared__ unsigned long long sWr2[NKP * DOUT];
    __shared__ float sb[DOUT];

    for (int idx = threadIdx.x; idx < NKP * DOUT; idx += 256) {
        int kp = idx / DOUT, c = idx % DOUT;
        sWl2[idx] = pack_f32(Wl[(2 * kp) * DOUT + c], Wl[(2 * kp + 1) * DOUT + c]);
        sWr2[idx] = pack_f32(Wr[(2 * kp) * DOUT + c], Wr[(2 * kp + 1) * DOUT + c]);
    }
    if (threadIdx.x < DOUT) sb[threadIdx.x] = bl[threadIdx.x];
    __syncthreads();

    int w     = threadIdx.x >> 5;
    int lane  = threadIdx.x & 31;
    int grp   = lane / DOUT;          // 0..NG-1
    int col   = lane % DOUT;
    int lg    = lane % WIDTH;         // lane within shuffle group
    int kbase = (lg % SRC_CNT) * KPL; // first k-pair this lane holds
    int wbase = blockIdx.x * NPB + w * NPW;

    // load h into registers as packed k-pairs {h[2kp], h[2kp+1]}
    unsigned long long hreg[NJ][KPL];
    #pragma unroll
    for (int j = 0; j < NJ; j++) {
        int node = wbase + j * NG + grp;
        #pragma unroll
        for (int u = 0; u < KPL; u++) {
            float2 v = make_float2(0.f, 0.f);
            if (node < n) {
                v = *reinterpret_cast<const float2*>(
                    h + (size_t)node * DIN + (kbase + u) * 2);
                if (RELU_IN) { v.x = fmaxf(v.x, 0.f); v.y = fmaxf(v.y, 0.f); }
            }
            hreg[j][u] = pack_f32(v.x, v.y);
        }
    }

    unsigned long long accl[NJ], accr[NJ];
    #pragma unroll
    for (int j = 0; j < NJ; j++) { accl[j] = 0ull; accr[j] = 0ull; }

    #pragma unroll
    for (int src = 0; src < SRC_CNT; src++) {
        #pragma unroll
        for (int u = 0; u < KPL; u++) {
            int kp = src * KPL + u;
            unsigned long long wl = sWl2[kp * DOUT + col];
            unsigned long long wr = sWr2[kp * DOUT + col];
            #pragma unroll
            for (int j = 0; j < NJ; j++) {
                unsigned long long a =
                    __shfl_sync(0xffffffffu, hreg[j][u], src, WIDTH);
                accl[j] = fma_f32x2(a, wl, accl[j]);
                accr[j] = fma_f32x2(a, wr, accr[j]);
            }
        }
    }

    float bias = sb[col];
    #pragma unroll
    for (int j = 0; j < NJ; j++) {
        int node = wbase + j * NG + grp;
        if (node < n) {
            float2 vl = unpack_f32x2(accl[j]);
            float2 vr = unpack_f32x2(accr[j]);
            p  [(size_t)node * DOUT + col] = __float2half_rn(vl.x + vl.y);
            out[(size_t)node * DOUT + col] = vr.x + vr.y + bias;
        }
    }
}

// ---------------------------------------------------------------------------
// out[node] += inv_deg[node] * mean-sum of fp16 p rows. Warp per node.
template <int DOUT>
__global__ __launch_bounds__(256) void aggregate_kernel(
    const __half* __restrict__ p, float* __restrict__ out, int n)
{
    constexpr int HPL = DOUT / 4;
    int lane = threadIdx.x & 31;
    int node = (blockIdx.x * blockDim.x + threadIdx.x) >> 5;
    if (node >= n) return;

    int beg = g_off[node];
    int pad = g_off[node + 1] - beg;       // multiple of 8
    int r = lane >> 2;
    int c = lane & 3;

    float f[HPL];
    #pragma unroll
    for (int q = 0; q < HPL; q++) f[q] = 0.f;

    for (int k = 0; k < pad; k += 8) {
        int4 iv0 = __ldg(reinterpret_cast<const int4*>(g_csrc + beg + k));
        int4 iv1 = __ldg(reinterpret_cast<const int4*>(g_csrc + beg + k + 4));
        int s = (r < 4) ? sel4(iv0, r) : sel4(iv1, r - 4);
        if (DOUT == 32) {
            uint4 v = __ldg(reinterpret_cast<const uint4*>(p + (size_t)s * 32) + c);
            const __half2* h2 = reinterpret_cast<const __half2*>(&v);
            #pragma unroll
            for (int q = 0; q < 4; q++) {
                float2 fv = __half22float2(h2[q]);
                f[2 * q]     += fv.x;
                f[2 * q + 1] += fv.y;
            }
        } else {
            uint2 v = __ldg(reinterpret_cast<const uint2*>(p + (size_t)s * 16) + c);
            const __half2* h2 = reinterpret_cast<const __half2*>(&v);
            #pragma unroll
            for (int q = 0; q < 2; q++) {
                float2 fv = __half22float2(h2[q]);
                f[2 * q]     += fv.x;
                f[2 * q + 1] += fv.y;
            }
        }
    }
    #pragma unroll
    for (int o = 4; o < 32; o <<= 1) {
        #pragma unroll
        for (int q = 0; q < HPL; q++)
            f[q] += __shfl_xor_sync(0xffffffffu, f[q], o);
    }
    if (lane < 4) {
        float inv = g_inv[node];
        float* ob = out + (size_t)node * DOUT + lane * HPL;
        if (DOUT == 32) {
            float4* o4 = reinterpret_cast<float4*>(ob);
            float4 a = o4[0], b = o4[1];
            a.x += f[0] * inv; a.y += f[1] * inv; a.z += f[2] * inv; a.w += f[3] * inv;
            b.x += f[4] * inv; b.y += f[5] * inv; b.z += f[6] * inv; b.w += f[7] * inv;
            o4[0] = a; o4[1] = b;
        } else {
            float4* o4 = reinterpret_cast<float4*>(ob);
            float4 a = o4[0];
            a.x += f[0] * inv; a.y += f[1] * inv; a.z += f[2] * inv; a.w += f[3] * inv;
            o4[0] = a;
        }
    }
}

// ---------------------------------------------------------------------------
extern "C" void kernel_launch(void* const* d_in, const int* in_sizes, int n_in,
                              void* d_out, int out_size)
{
    const float* x  = (const float*)d_in[0];
    const void*  ei = d_in[1];
    const float *Wl[6], *bl[6], *Wr[6];
    for (int i = 0; i < 6; i++) {
        Wl[i] = (const float*)d_in[2 + 3 * i];
        bl[i] = (const float*)d_in[3 + 3 * i];
        Wr[i] = (const float*)d_in[4 + 3 * i];
    }
    float* out = (float*)d_out;
    const int n = NN, e = EE;

    __half* pp = nullptr;
    float *ph0 = nullptr, *ph1 = nullptr;
    cudaGetSymbolAddress((void**)&pp,  g_p);
    cudaGetSymbolAddress((void**)&ph0, g_h0);
    cudaGetSymbolAddress((void**)&ph1, g_h1);

    // nodes/block: L0 (NJ=2,NG=1): 16 ; small (NJ=4,NG=1): 32 ; L5 (NJ=4,NG=2): 64
    const int G0  = (n + 15) / 16;
    const int GS  = (n + 31) / 32;
    const int G5  = (n + 63) / 64;
    const int blocksA = (n * 32 + 255) / 256;

    // ---- launch sequence (gemm0 placed 4th for ncu attribution) ----
    zero_deg_kernel<<<(n + 255) / 256, 256>>>(n);
    detect_kernel<<<1, 128>>>((const long long*)ei, n);
    prep_kernel<<<(e + 255) / 256, 256>>>(ei, e, n);
    gemm_fused<128, 32, false, 2><<<G0, 256>>>(x, Wl[0], Wr[0], bl[0], pp, ph0, n);
    scan_blocks_kernel<<<SCAN_NB, 1024>>>(n);
    scan_bsums_kernel<<<1, 128>>>(SCAN_NB, n);
    finalize_offsets_kernel<<<SCAN_NB, 1024>>>(n);
    fill_kernel<<<(e + 255) / 256, 256>>>(e);
    pad_tails_kernel<<<(n + 255) / 256, 256>>>(pp, n);

    aggregate_kernel<32><<<blocksA, 256>>>(pp, ph0, n);
    gemm_fused<32, 32, true, 4><<<GS, 256>>>(ph0, Wl[1], Wr[1], bl[1], pp, ph1, n);
    aggregate_kernel<32><<<blocksA, 256>>>(pp, ph1, n);
    gemm_fused<32, 32, true, 4><<<GS, 256>>>(ph1, Wl[2], Wr[2], bl[2], pp, ph0, n);
    aggregate_kernel<32><<<blocksA, 256>>>(pp, ph0, n);
    gemm_fused<32, 32, true, 4><<<GS, 256>>>(ph0, Wl[3], Wr[3], bl[3], pp, ph1, n);
    aggregate_kernel<32><<<blocksA, 256>>>(pp, ph1, n);
    gemm_fused<32, 32, true, 4><<<GS, 256>>>(ph1, Wl[4], Wr[4], bl[4], pp, ph0, n);
    aggregate_kernel<32><<<blocksA, 256>>>(pp, ph0, n);
    gemm_fused<32, 16, true, 4><<<G5, 256>>>(ph0, Wl[5], Wr[5], bl[5], pp, out, n);
    zero_prow16_kernel<<<1, 16>>>(pp);
    aggregate_kernel<16><<<blocksA, 256>>>(pp, out, n);
}

// round 11
// speedup vs baseline: 1.3781x; 1.1267x over previous
#include <cuda_runtime.h>
#include <cuda_fp16.h>

// GraphSAGE 6-layer: dims 128->32->32->32->32->32->16
//  R11: GEMM v3 — no shuffles. h staged raw in smem (LDS.128 broadcast reads,
//       a 16B load IS two packed k-pairs), W staged as ulonglong2 {wl,wr}
//       (one LDS.128 per k-pair for both paths), NJ=4/8 nodes amortize W.
//       MIO:FMA drops 1.5 -> 0.375. Aggregation (fp16) + CSR unchanged.

#define NN 100000
#define EE 3200000
#define CSRSZ (EE + 8 * NN)
#define SCAN_NB ((NN + 1023) / 1024)   // 98 blocks

__device__ int    g_is32;
__device__ int    g_srcc[EE];
__device__ int    g_dstc[EE];
__device__ int    g_csrc[CSRSZ];
__device__ int    g_deg[NN];
__device__ int    g_cur[NN];
__device__ int    g_off[NN + 1];
__device__ int    g_bsum[128];
__device__ int    g_boff[128];
__device__ float  g_inv[NN];
__device__ __half g_p [(NN + 1) * 32];   // fp16 messages; row NN = zero sentinel
__device__ float  g_h0[NN * 32];
__device__ float  g_h1[NN * 32];

// ---------------------------------------------------------------------------
// packed f32x2 helpers (sm_100+)
__device__ __forceinline__ unsigned long long fma_f32x2(
    unsigned long long a, unsigned long long b, unsigned long long c) {
    unsigned long long d;
    asm("fma.rn.f32x2 %0, %1, %2, %3;" : "=l"(d) : "l"(a), "l"(b), "l"(c));
    return d;
}
__device__ __forceinline__ unsigned long long pack_f32(float lo, float hi) {
    unsigned long long r;
    asm("mov.b64 %0, {%1, %2};" : "=l"(r) : "f"(lo), "f"(hi));
    return r;
}
__device__ __forceinline__ float2 unpack_f32x2(unsigned long long v) {
    float2 r;
    asm("mov.b64 {%0, %1}, %2;" : "=f"(r.x), "=f"(r.y) : "l"(v));
    return r;
}
__device__ __forceinline__ int sel4(const int4& v, int r) {
    return (r == 0) ? v.x : (r == 1) ? v.y : (r == 2) ? v.z : v.w;
}

// ---------------------------------------------------------------------------
__global__ void detect_kernel(const long long* __restrict__ ei, int n) {
    __shared__ int s_bad;
    if (threadIdx.x == 0) s_bad = 0;
    __syncthreads();
    long long v = ei[threadIdx.x];
    if (v < 0 || v >= (long long)n) atomicAdd(&s_bad, 1);
    __syncthreads();
    if (threadIdx.x == 0) g_is32 = (s_bad > 0) ? 1 : 0;
}

__global__ void zero_deg_kernel(int n) {
    int i = blockIdx.x * blockDim.x + threadIdx.x;
    if (i < n) g_deg[i] = 0;
}

__global__ void prep_kernel(const void* __restrict__ eiv, int e, int n) {
    int i = blockIdx.x * blockDim.x + threadIdx.x;
    if (i >= e) return;
    int s, d;
    if (g_is32) {
        const int* p = (const int*)eiv;
        s = p[i];
        d = p[e + i];
    } else {
        const long long* p = (const long long*)eiv;
        s = (int)p[i];
        d = (int)p[(size_t)e + i];
    }
    if ((unsigned)s >= (unsigned)n || (unsigned)d >= (unsigned)n) {
        g_srcc[i] = -1;
        g_dstc[i] = -1;
        return;
    }
    g_srcc[i] = s;
    g_dstc[i] = d;
    atomicAdd(&g_deg[d], 1);
}

// Hierarchical scan over PADDED degrees ((deg+7)&~7).
__global__ __launch_bounds__(1024) void scan_blocks_kernel(int n) {
    __shared__ int s_wsum[32];
    int i    = blockIdx.x * 1024 + threadIdx.x;
    int lane = threadIdx.x & 31;
    int w    = threadIdx.x >> 5;
    int v = (i < n) ? ((g_deg[i] + 7) & ~7) : 0;
    int x = v;
    #pragma unroll
    for (int o = 1; o < 32; o <<= 1) {
        int t = __shfl_up_sync(0xffffffffu, x, o);
        if (lane >= o) x += t;
    }
    if (lane == 31) s_wsum[w] = x;
    __syncthreads();
    if (w == 0) {
        int ws = s_wsum[lane];
        #pragma unroll
        for (int o = 1; o < 32; o <<= 1) {
            int t = __shfl_up_sync(0xffffffffu, ws, o);
            if (lane >= o) ws += t;
        }
        s_wsum[lane] = ws;
    }
    __syncthreads();
    int incl = x + ((w == 0) ? 0 : s_wsum[w - 1]);
    if (i < n) g_off[i] = incl - v;
    if (threadIdx.x == 1023) g_bsum[blockIdx.x] = incl;
}

__global__ void scan_bsums_kernel(int nb, int n) {
    __shared__ int s_wsum[4];
    int lane = threadIdx.x & 31;
    int w    = threadIdx.x >> 5;
    int v = (threadIdx.x < nb) ? g_bsum[threadIdx.x] : 0;
    int x = v;
    #pragma unroll
    for (int o = 1; o < 32; o <<= 1) {
        int t = __shfl_up_sync(0xffffffffu, x, o);
        if (lane >= o) x += t;
    }
    if (lane == 31) s_wsum[w] = x;
    __syncthreads();
    if (w == 0 && lane < 4) {
        int ws = s_wsum[lane];
        #pragma unroll
        for (int o = 1; o < 4; o <<= 1) {
            int t = __shfl_up_sync(0x0000000fu, ws, o);
            if (lane >= o) ws += t;
        }
        s_wsum[lane] = ws;
    }
    __syncthreads();
    int incl = x + ((w == 0) ? 0 : s_wsum[w - 1]);
    g_boff[threadIdx.x] = incl - v;
    if (threadIdx.x == 127) g_off[n] = incl;
}

__global__ __launch_bounds__(1024) void finalize_offsets_kernel(int n) {
    int i = blockIdx.x * 1024 + threadIdx.x;
    if (i < n) {
        int off = g_off[i] + g_boff[blockIdx.x];
        g_off[i] = off;
        g_cur[i] = off;
        int v = g_deg[i];
        g_inv[i] = 1.0f / (float)(v > 0 ? v : 1);
    }
}

__global__ void fill_kernel(int e) {
    int i = blockIdx.x * blockDim.x + threadIdx.x;
    if (i < e) {
        int d = g_dstc[i];
        if (d < 0) return;
        int slot = atomicAdd(&g_cur[d], 1);
        if (slot >= 0 && slot < CSRSZ) g_csrc[slot] = g_srcc[i];
    }
}

// write sentinel into pad gaps; zero the DOUT=32 sentinel row
__global__ void pad_tails_kernel(__half* p16, int n) {
    int i = blockIdx.x * blockDim.x + threadIdx.x;
    if (i < n) {
        int end = g_off[i + 1];
        for (int j = g_cur[i]; j < end; j++)
            if (j >= 0 && j < CSRSZ) g_csrc[j] = NN;
    }
    if (blockIdx.x == 0 && threadIdx.x < 32)
        p16[(size_t)NN * 32 + threadIdx.x] = __float2half(0.f);
}

__global__ void zero_prow16_kernel(__half* p16) {
    p16[(size_t)NN * 16 + threadIdx.x] = __float2half(0.f);
}

// ---------------------------------------------------------------------------
// Fused dual GEMM v3: p = fp16(relu?(h) @ Wl); out = relu?(h) @ Wr + bl.
// smem: sW[kp*DOUT+col] = ulonglong2{ {Wl[2kp],Wl[2kp+1]}, {Wr[2kp],Wr[2kp+1]} },
//       sh = raw h tile (relu applied). Inner iter covers 2 k-pairs:
//       2 LDS.128 (W) + NJ LDS.128 (h broadcast) + 4*NJ FFMA2.
template <int DIN, int DOUT, bool RELU_IN, int NJ>
__global__ __launch_bounds__(256) void gemm_fused(
    const float* __restrict__ h,
    const float* __restrict__ Wl, const float* __restrict__ Wr,
    const float* __restrict__ bl,
    __half* __restrict__ p, float* __restrict__ out, int n)
{
    constexpr int NG  = 32 / DOUT;     // lane groups per warp (1 or 2)
    constexpr int NPW = NJ * NG;       // nodes per warp
    constexpr int NPB = 8 * NPW;       // nodes per block
    constexpr int NKP = DIN / 2;       // k-pairs
    constexpr int NI  = DIN / 4;       // inner iterations (2 k-pairs each)

    extern __shared__ unsigned char smem_raw[];
    ulonglong2* sW = reinterpret_cast<ulonglong2*>(smem_raw);          // NKP*DOUT
    float*      sh = reinterpret_cast<float*>(smem_raw + (size_t)NKP * DOUT * 16);
    float*      sb = sh + NPB * DIN;

    // stage W packed {wl_kpair, wr_kpair}
    for (int idx = threadIdx.x; idx < NKP * DOUT; idx += 256) {
        int kp = idx / DOUT, c = idx % DOUT;
        ulonglong2 t;
        t.x = pack_f32(Wl[(2 * kp) * DOUT + c], Wl[(2 * kp + 1) * DOUT + c]);
        t.y = pack_f32(Wr[(2 * kp) * DOUT + c], Wr[(2 * kp + 1) * DOUT + c]);
        sW[idx] = t;
    }
    if (threadIdx.x < DOUT) sb[threadIdx.x] = bl[threadIdx.x];

    // stage h tile (float4 vectorized, relu applied, zero-fill OOB)
    int bbase = blockIdx.x * NPB;
    {
        constexpr int TOT4 = NPB * DIN / 4;
        const float4* hg = reinterpret_cast<const float4*>(h) + (size_t)bbase * (DIN / 4);
        long rem = ((long)n - bbase) * (DIN / 4);
        int lim4 = (rem <= 0) ? 0 : (rem < TOT4 ? (int)rem : TOT4);
        float4* sh4 = reinterpret_cast<float4*>(sh);
        for (int idx = threadIdx.x; idx < TOT4; idx += 256) {
            float4 v = make_float4(0.f, 0.f, 0.f, 0.f);
            if (idx < lim4) {
                v = hg[idx];
                if (RELU_IN) {
                    v.x = fmaxf(v.x, 0.f); v.y = fmaxf(v.y, 0.f);
                    v.z = fmaxf(v.z, 0.f); v.w = fmaxf(v.w, 0.f);
                }
            }
            sh4[idx] = v;
        }
    }
    __syncthreads();

    int w    = threadIdx.x >> 5;
    int lane = threadIdx.x & 31;
    int grp  = lane / DOUT;       // 0..NG-1
    int col  = lane % DOUT;

    unsigned long long accl[NJ], accr[NJ];
    #pragma unroll
    for (int j = 0; j < NJ; j++) { accl[j] = 0ull; accr[j] = 0ull; }

    #pragma unroll 4
    for (int it = 0; it < NI; it++) {
        ulonglong2 w0 = sW[(2 * it) * DOUT + col];
        ulonglong2 w1 = sW[(2 * it + 1) * DOUT + col];
        #pragma unroll
        for (int j = 0; j < NJ; j++) {
            int nl = w * NPW + j * NG + grp;   // local node index
            ulonglong2 hh = *reinterpret_cast<const ulonglong2*>(
                sh + nl * DIN + it * 4);
            accl[j] = fma_f32x2(hh.x, w0.x, accl[j]);
            accr[j] = fma_f32x2(hh.x, w0.y, accr[j]);
            accl[j] = fma_f32x2(hh.y, w1.x, accl[j]);
            accr[j] = fma_f32x2(hh.y, w1.y, accr[j]);
        }
    }

    float bias = sb[col];
    #pragma unroll
    for (int j = 0; j < NJ; j++) {
        int node = bbase + w * NPW + j * NG + grp;
        if (node < n) {
            float2 vl = unpack_f32x2(accl[j]);
            float2 vr = unpack_f32x2(accr[j]);
            p  [(size_t)node * DOUT + col] = __float2half_rn(vl.x + vl.y);
            out[(size_t)node * DOUT + col] = vr.x + vr.y + bias;
        }
    }
}

// ---------------------------------------------------------------------------
// out[node] += inv_deg[node] * mean-sum of fp16 p rows. Warp per node.
template <int DOUT>
__global__ __launch_bounds__(256) void aggregate_kernel(
    const __half* __restrict__ p, float* __restrict__ out, int n)
{
    constexpr int HPL = DOUT / 4;
    int lane = threadIdx.x & 31;
    int node = (blockIdx.x * blockDim.x + threadIdx.x) >> 5;
    if (node >= n) return;

    int beg = g_off[node];
    int pad = g_off[node + 1] - beg;       // multiple of 8
    int r = lane >> 2;
    int c = lane & 3;

    float f[HPL];
    #pragma unroll
    for (int q = 0; q < HPL; q++) f[q] = 0.f;

    for (int k = 0; k < pad; k += 8) {
        int4 iv0 = __ldg(reinterpret_cast<const int4*>(g_csrc + beg + k));
        int4 iv1 = __ldg(reinterpret_cast<const int4*>(g_csrc + beg + k + 4));
        int s = (r < 4) ? sel4(iv0, r) : sel4(iv1, r - 4);
        if (DOUT == 32) {
            uint4 v = __ldg(reinterpret_cast<const uint4*>(p + (size_t)s * 32) + c);
            const __half2* h2 = reinterpret_cast<const __half2*>(&v);
            #pragma unroll
            for (int q = 0; q < 4; q++) {
                float2 fv = __half22float2(h2[q]);
                f[2 * q]     += fv.x;
                f[2 * q + 1] += fv.y;
            }
        } else {
            uint2 v = __ldg(reinterpret_cast<const uint2*>(p + (size_t)s * 16) + c);
            const __half2* h2 = reinterpret_cast<const __half2*>(&v);
            #pragma unroll
            for (int q = 0; q < 2; q++) {
                float2 fv = __half22float2(h2[q]);
                f[2 * q]     += fv.x;
                f[2 * q + 1] += fv.y;
            }
        }
    }
    #pragma unroll
    for (int o = 4; o < 32; o <<= 1) {
        #pragma unroll
        for (int q = 0; q < HPL; q++)
            f[q] += __shfl_xor_sync(0xffffffffu, f[q], o);
    }
    if (lane < 4) {
        float inv = g_inv[node];
        float* ob = out + (size_t)node * DOUT + lane * HPL;
        if (DOUT == 32) {
            float4* o4 = reinterpret_cast<float4*>(ob);
            float4 a = o4[0], b = o4[1];
            a.x += f[0] * inv; a.y += f[1] * inv; a.z += f[2] * inv; a.w += f[3] * inv;
            b.x += f[4] * inv; b.y += f[5] * inv; b.z += f[6] * inv; b.w += f[7] * inv;
            o4[0] = a; o4[1] = b;
        } else {
            float4* o4 = reinterpret_cast<float4*>(ob);
            float4 a = o4[0];
            a.x += f[0] * inv; a.y += f[1] * inv; a.z += f[2] * inv; a.w += f[3] * inv;
            o4[0] = a;
        }
    }
}

// ---------------------------------------------------------------------------
extern "C" void kernel_launch(void* const* d_in, const int* in_sizes, int n_in,
                              void* d_out, int out_size)
{
    const float* x  = (const float*)d_in[0];
    const void*  ei = d_in[1];
    const float *Wl[6], *bl[6], *Wr[6];
    for (int i = 0; i < 6; i++) {
        Wl[i] = (const float*)d_in[2 + 3 * i];
        bl[i] = (const float*)d_in[3 + 3 * i];
        Wr[i] = (const float*)d_in[4 + 3 * i];
    }
    float* out = (float*)d_out;
    const int n = NN, e = EE;

    __half* pp = nullptr;
    float *ph0 = nullptr, *ph1 = nullptr;
    cudaGetSymbolAddress((void**)&pp,  g_p);
    cudaGetSymbolAddress((void**)&ph0, g_h0);
    cudaGetSymbolAddress((void**)&ph1, g_h1);

    // dynamic smem: sW + sh + sb
    // L0 (128,32,NJ=4):  64*32*16 + 32*128*4 + 32*4 = 49280
    // LS (32,32,NJ=8):   16*32*16 + 64*32*4  + 32*4 = 16512
    // L5 (32,16,NJ=4):   16*16*16 + 64*32*4  + 16*4 = 12352
    const int SM_L0 = 64 * 32 * 16 + 32 * 128 * 4 + 32 * 4;
    const int SM_LS = 16 * 32 * 16 + 64 * 32 * 4 + 32 * 4;
    const int SM_L5 = 16 * 16 * 16 + 64 * 32 * 4 + 16 * 4;
    cudaFuncSetAttribute(gemm_fused<128, 32, false, 4>,
                         cudaFuncAttributeMaxDynamicSharedMemorySize, SM_L0);
    cudaFuncSetAttribute(gemm_fused<32, 32, true, 8>,
                         cudaFuncAttributeMaxDynamicSharedMemorySize, SM_LS);
    cudaFuncSetAttribute(gemm_fused<32, 16, true, 4>,
                         cudaFuncAttributeMaxDynamicSharedMemorySize, SM_L5);

    // nodes/block: L0: 32 ; small: 64 ; L5: 64
    const int G0  = (n + 31) / 32;
    const int GS  = (n + 63) / 64;
    const int G5  = (n + 63) / 64;
    const int blocksA = (n * 32 + 255) / 256;

    // ---- launch sequence (gemm0 placed 4th for ncu attribution) ----
    zero_deg_kernel<<<(n + 255) / 256, 256>>>(n);
    detect_kernel<<<1, 128>>>((const long long*)ei, n);
    prep_kernel<<<(e + 255) / 256, 256>>>(ei, e, n);
    gemm_fused<128, 32, false, 4><<<G0, 256, SM_L0>>>(x, Wl[0], Wr[0], bl[0], pp, ph0, n);
    scan_blocks_kernel<<<SCAN_NB, 1024>>>(n);
    scan_bsums_kernel<<<1, 128>>>(SCAN_NB, n);
    finalize_offsets_kernel<<<SCAN_NB, 1024>>>(n);
    fill_kernel<<<(e + 255) / 256, 256>>>(e);
    pad_tails_kernel<<<(n + 255) / 256, 256>>>(pp, n);

    aggregate_kernel<32><<<blocksA, 256>>>(pp, ph0, n);
    gemm_fused<32, 32, true, 8><<<GS, 256, SM_LS>>>(ph0, Wl[1], Wr[1], bl[1], pp, ph1, n);
    aggregate_kernel<32><<<blocksA, 256>>>(pp, ph1, n);
    gemm_fused<32, 32, true, 8><<<GS, 256, SM_LS>>>(ph1, Wl[2], Wr[2], bl[2], pp, ph0, n);
    aggregate_kernel<32><<<blocksA, 256>>>(pp, ph0, n);
    gemm_fused<32, 32, true, 8><<<GS, 256, SM_LS>>>(ph0, Wl[3], Wr[3], bl[3], pp, ph1, n);
    aggregate_kernel<32><<<blocksA, 256>>>(pp, ph1, n);
    gemm_fused<32, 32, true, 8><<<GS, 256, SM_LS>>>(ph1, Wl[4], Wr[4], bl[4], pp, ph0, n);
    aggregate_kernel<32><<<blocksA, 256>>>(pp, ph0, n);
    gemm_fused<32, 16, true, 4><<<G5, 256, SM_L5>>>(ph0, Wl[5], Wr[5], bl[5], pp, out, n);
    zero_prow16_kernel<<<1, 16>>>(pp);
    aggregate_kernel<16><<<blocksA, 256>>>(pp, out, n);
}

// round 13
// speedup vs baseline: 1.3827x; 1.0033x over previous
#include <cuda_runtime.h>
#include <cuda_fp16.h>

// GraphSAGE 6-layer: dims 128->32->32->32->32->32->16
//  R13 = R12 resubmit (container-level infra failure, no kernel signal):
//       gemm0 NJ=8 @512 threads (halves W crossbar traffic per node);
//       fill reads edge_index directly (g_srcc/g_dstc eliminated);
//       DOUT=16 sentinel zero folded into gemm L5 epilogue.

#define NN 100000
#define EE 3200000
#define CSRSZ (EE + 8 * NN)
#define SCAN_NB ((NN + 1023) / 1024)   // 98 blocks

__device__ int    g_is32;
__device__ int    g_csrc[CSRSZ];
__device__ int    g_deg[NN];
__device__ int    g_cur[NN];
__device__ int    g_off[NN + 1];
__device__ int    g_bsum[128];
__device__ int    g_boff[128];
__device__ float  g_inv[NN];
__device__ __half g_p [(NN + 1) * 32];   // fp16 messages; row NN = zero sentinel
__device__ float  g_h0[NN * 32];
__device__ float  g_h1[NN * 32];

// ---------------------------------------------------------------------------
// packed f32x2 helpers (sm_100+)
__device__ __forceinline__ unsigned long long fma_f32x2(
    unsigned long long a, unsigned long long b, unsigned long long c) {
    unsigned long long d;
    asm("fma.rn.f32x2 %0, %1, %2, %3;" : "=l"(d) : "l"(a), "l"(b), "l"(c));
    return d;
}
__device__ __forceinline__ unsigned long long pack_f32(float lo, float hi) {
    unsigned long long r;
    asm("mov.b64 %0, {%1, %2};" : "=l"(r) : "f"(lo), "f"(hi));
    return r;
}
__device__ __forceinline__ float2 unpack_f32x2(unsigned long long v) {
    float2 r;
    asm("mov.b64 {%0, %1}, %2;" : "=f"(r.x), "=f"(r.y) : "l"(v));
    return r;
}
__device__ __forceinline__ int sel4(const int4& v, int r) {
    return (r == 0) ? v.x : (r == 1) ? v.y : (r == 2) ? v.z : v.w;
}

// ---------------------------------------------------------------------------
__global__ void detect_kernel(const long long* __restrict__ ei, int n) {
    __shared__ int s_bad;
    if (threadIdx.x == 0) s_bad = 0;
    __syncthreads();
    long long v = ei[threadIdx.x];
    if (v < 0 || v >= (long long)n) atomicAdd(&s_bad, 1);
    __syncthreads();
    if (threadIdx.x == 0) g_is32 = (s_bad > 0) ? 1 : 0;
}

__global__ void zero_deg_kernel(int n) {
    int i = blockIdx.x * blockDim.x + threadIdx.x;
    if (i < n) g_deg[i] = 0;
}

// count in-degree straight from edge_index
__global__ void prep_kernel(const void* __restrict__ eiv, int e, int n) {
    int i = blockIdx.x * blockDim.x + threadIdx.x;
    if (i >= e) return;
    int d;
    if (g_is32) {
        d = ((const int*)eiv)[e + i];
    } else {
        d = (int)((const long long*)eiv)[(size_t)e + i];
    }
    if ((unsigned)d < (unsigned)n) atomicAdd(&g_deg[d], 1);
}

// Hierarchical scan over PADDED degrees ((deg+7)&~7).
__global__ __launch_bounds__(1024) void scan_blocks_kernel(int n) {
    __shared__ int s_wsum[32];
    int i    = blockIdx.x * 1024 + threadIdx.x;
    int lane = threadIdx.x & 31;
    int w    = threadIdx.x >> 5;
    int v = (i < n) ? ((g_deg[i] + 7) & ~7) : 0;
    int x = v;
    #pragma unroll
    for (int o = 1; o < 32; o <<= 1) {
        int t = __shfl_up_sync(0xffffffffu, x, o);
        if (lane >= o) x += t;
    }
    if (lane == 31) s_wsum[w] = x;
    __syncthreads();
    if (w == 0) {
        int ws = s_wsum[lane];
        #pragma unroll
        for (int o = 1; o < 32; o <<= 1) {
            int t = __shfl_up_sync(0xffffffffu, ws, o);
            if (lane >= o) ws += t;
        }
        s_wsum[lane] = ws;
    }
    __syncthreads();
    int incl = x + ((w == 0) ? 0 : s_wsum[w - 1]);
    if (i < n) g_off[i] = incl - v;
    if (threadIdx.x == 1023) g_bsum[blockIdx.x] = incl;
}

__global__ void scan_bsums_kernel(int nb, int n) {
    __shared__ int s_wsum[4];
    int lane = threadIdx.x & 31;
    int w    = threadIdx.x >> 5;
    int v = (threadIdx.x < nb) ? g_bsum[threadIdx.x] : 0;
    int x = v;
    #pragma unroll
    for (int o = 1; o < 32; o <<= 1) {
        int t = __shfl_up_sync(0xffffffffu, x, o);
        if (lane >= o) x += t;
    }
    if (lane == 31) s_wsum[w] = x;
    __syncthreads();
    if (w == 0 && lane < 4) {
        int ws = s_wsum[lane];
        #pragma unroll
        for (int o = 1; o < 4; o <<= 1) {
            int t = __shfl_up_sync(0x0000000fu, ws, o);
            if (lane >= o) ws += t;
        }
        s_wsum[lane] = ws;
    }
    __syncthreads();
    int incl = x + ((w == 0) ? 0 : s_wsum[w - 1]);
    g_boff[threadIdx.x] = incl - v;
    if (threadIdx.x == 127) g_off[n] = incl;
}

__global__ __launch_bounds__(1024) void finalize_offsets_kernel(int n) {
    int i = blockIdx.x * 1024 + threadIdx.x;
    if (i < n) {
        int off = g_off[i] + g_boff[blockIdx.x];
        g_off[i] = off;
        g_cur[i] = off;
        int v = g_deg[i];
        g_inv[i] = 1.0f / (float)(v > 0 ? v : 1);
    }
}

// bucket src indices by dst, reading edge_index directly (L2-resident after prep)
__global__ void fill_kernel(const void* __restrict__ eiv, int e, int n) {
    int i = blockIdx.x * blockDim.x + threadIdx.x;
    if (i >= e) return;
    int s, d;
    if (g_is32) {
        const int* p = (const int*)eiv;
        s = p[i];
        d = p[e + i];
    } else {
        const long long* p = (const long long*)eiv;
        s = (int)p[i];
        d = (int)p[(size_t)e + i];
    }
    if ((unsigned)s >= (unsigned)n || (unsigned)d >= (unsigned)n) return;
    int slot = atomicAdd(&g_cur[d], 1);
    if (slot >= 0 && slot < CSRSZ) g_csrc[slot] = s;
}

// write sentinel into pad gaps; zero the DOUT=32 sentinel row
__global__ void pad_tails_kernel(__half* p16, int n) {
    int i = blockIdx.x * blockDim.x + threadIdx.x;
    if (i < n) {
        int end = g_off[i + 1];
        for (int j = g_cur[i]; j < end; j++)
            if (j >= 0 && j < CSRSZ) g_csrc[j] = NN;
    }
    if (blockIdx.x == 0 && threadIdx.x < 32)
        p16[(size_t)NN * 32 + threadIdx.x] = __float2half(0.f);
}

// ---------------------------------------------------------------------------
// Fused dual GEMM v4: p = fp16(relu?(h) @ Wl); out = relu?(h) @ Wr + bl.
// sW[kp*DOUT+col] = ulonglong2{ {Wl[2kp],Wl[2kp+1]}, {Wr[2kp],Wr[2kp+1]} };
// sh = raw h tile. NTHR threads; NJ nodes per lane group.
// ZSENT: block 0 additionally zeros the DOUT=16 sentinel row of p.
template <int DIN, int DOUT, bool RELU_IN, int NJ, int NTHR, bool ZSENT>
__global__ __launch_bounds__(NTHR) void gemm_fused(
    const float* __restrict__ h,
    const float* __restrict__ Wl, const float* __restrict__ Wr,
    const float* __restrict__ bl,
    __half* __restrict__ p, float* __restrict__ out, int n)
{
    constexpr int NG    = 32 / DOUT;     // lane groups per warp (1 or 2)
    constexpr int NWARP = NTHR / 32;
    constexpr int NPW   = NJ * NG;       // nodes per warp
    constexpr int NPB   = NWARP * NPW;   // nodes per block
    constexpr int NKP   = DIN / 2;       // k-pairs
    constexpr int NI    = DIN / 4;       // inner iterations (2 k-pairs each)

    extern __shared__ unsigned char smem_raw[];
    ulonglong2* sW = reinterpret_cast<ulonglong2*>(smem_raw);          // NKP*DOUT
    float*      sh = reinterpret_cast<float*>(smem_raw + (size_t)NKP * DOUT * 16);
    float*      sb = sh + NPB * DIN;

    for (int idx = threadIdx.x; idx < NKP * DOUT; idx += NTHR) {
        int kp = idx / DOUT, c = idx % DOUT;
        ulonglong2 t;
        t.x = pack_f32(Wl[(2 * kp) * DOUT + c], Wl[(2 * kp + 1) * DOUT + c]);
        t.y = pack_f32(Wr[(2 * kp) * DOUT + c], Wr[(2 * kp + 1) * DOUT + c]);
        sW[idx] = t;
    }
    if (threadIdx.x < DOUT) sb[threadIdx.x] = bl[threadIdx.x];
    if (ZSENT && blockIdx.x == 0 && threadIdx.x >= 32 && threadIdx.x < 48)
        p[(size_t)NN * 16 + (threadIdx.x - 32)] = __float2half(0.f);

    int bbase = blockIdx.x * NPB;
    {
        constexpr int TOT4 = NPB * DIN / 4;
        const float4* hg = reinterpret_cast<const float4*>(h) + (size_t)bbase * (DIN / 4);
        long rem = ((long)n - bbase) * (DIN / 4);
        int lim4 = (rem <= 0) ? 0 : (rem < TOT4 ? (int)rem : TOT4);
        float4* sh4 = reinterpret_cast<float4*>(sh);
        for (int idx = threadIdx.x; idx < TOT4; idx += NTHR) {
            float4 v = make_float4(0.f, 0.f, 0.f, 0.f);
            if (idx < lim4) {
                v = hg[idx];
                if (RELU_IN) {
                    v.x = fmaxf(v.x, 0.f); v.y = fmaxf(v.y, 0.f);
                    v.z = fmaxf(v.z, 0.f); v.w = fmaxf(v.w, 0.f);
                }
            }
            sh4[idx] = v;
        }
    }
    __syncthreads();

    int w    = threadIdx.x >> 5;
    int lane = threadIdx.x & 31;
    int grp  = lane / DOUT;       // 0..NG-1
    int col  = lane % DOUT;

    unsigned long long accl[NJ], accr[NJ];
    #pragma unroll
    for (int j = 0; j < NJ; j++) { accl[j] = 0ull; accr[j] = 0ull; }

    #pragma unroll 4
    for (int it = 0; it < NI; it++) {
        ulonglong2 w0 = sW[(2 * it) * DOUT + col];
        ulonglong2 w1 = sW[(2 * it + 1) * DOUT + col];
        #pragma unroll
        for (int j = 0; j < NJ; j++) {
            int nl = w * NPW + j * NG + grp;   // local node index
            ulonglong2 hh = *reinterpret_cast<const ulonglong2*>(
                sh + nl * DIN + it * 4);
            accl[j] = fma_f32x2(hh.x, w0.x, accl[j]);
            accr[j] = fma_f32x2(hh.x, w0.y, accr[j]);
            accl[j] = fma_f32x2(hh.y, w1.x, accl[j]);
            accr[j] = fma_f32x2(hh.y, w1.y, accr[j]);
        }
    }

    float bias = sb[col];
    #pragma unroll
    for (int j = 0; j < NJ; j++) {
        int node = bbase + w * NPW + j * NG + grp;
        if (node < n) {
            float2 vl = unpack_f32x2(accl[j]);
            float2 vr = unpack_f32x2(accr[j]);
            p  [(size_t)node * DOUT + col] = __float2half_rn(vl.x + vl.y);
            out[(size_t)node * DOUT + col] = vr.x + vr.y + bias;
        }
    }
}

// ---------------------------------------------------------------------------
// out[node] += inv_deg[node] * mean-sum of fp16 p rows. Warp per node.
template <int DOUT>
__global__ __launch_bounds__(256) void aggregate_kernel(
    const __half* __restrict__ p, float* __restrict__ out, int n)
{
    constexpr int HPL = DOUT / 4;
    int lane = threadIdx.x & 31;
    int node = (blockIdx.x * blockDim.x + threadIdx.x) >> 5;
    if (node >= n) return;

    int beg = g_off[node];
    int pad = g_off[node + 1] - beg;       // multiple of 8
    int r = lane >> 2;
    int c = lane & 3;

    float f[HPL];
    #pragma unroll
    for (int q = 0; q < HPL; q++) f[q] = 0.f;

    for (int k = 0; k < pad; k += 8) {
        int4 iv0 = __ldg(reinterpret_cast<const int4*>(g_csrc + beg + k));
        int4 iv1 = __ldg(reinterpret_cast<const int4*>(g_csrc + beg + k + 4));
        int s = (r < 4) ? sel4(iv0, r) : sel4(iv1, r - 4);
        if (DOUT == 32) {
            uint4 v = __ldg(reinterpret_cast<const uint4*>(p + (size_t)s * 32) + c);
            const __half2* h2 = reinterpret_cast<const __half2*>(&v);
            #pragma unroll
            for (int q = 0; q < 4; q++) {
                float2 fv = __half22float2(h2[q]);
                f[2 * q]     += fv.x;
                f[2 * q + 1] += fv.y;
            }
        } else {
            uint2 v = __ldg(reinterpret_cast<const uint2*>(p + (size_t)s * 16) + c);
            const __half2* h2 = reinterpret_cast<const __half2*>(&v);
            #pragma unroll
            for (int q = 0; q < 2; q++) {
                float2 fv = __half22float2(h2[q]);
                f[2 * q]     += fv.x;
                f[2 * q + 1] += fv.y;
            }
        }
    }
    #pragma unroll
    for (int o = 4; o < 32; o <<= 1) {
        #pragma unroll
        for (int q = 0; q < HPL; q++)
            f[q] += __shfl_xor_sync(0xffffffffu, f[q], o);
    }
    if (lane < 4) {
        float inv = g_inv[node];
        float* ob = out + (size_t)node * DOUT + lane * HPL;
        if (DOUT == 32) {
            float4* o4 = reinterpret_cast<float4*>(ob);
            float4 a = o4[0], b = o4[1];
            a.x += f[0] * inv; a.y += f[1] * inv; a.z += f[2] * inv; a.w += f[3] * inv;
            b.x += f[4] * inv; b.y += f[5] * inv; b.z += f[6] * inv; b.w += f[7] * inv;
            o4[0] = a; o4[1] = b;
        } else {
            float4* o4 = reinterpret_cast<float4*>(ob);
            float4 a = o4[0];
            a.x += f[0] * inv; a.y += f[1] * inv; a.z += f[2] * inv; a.w += f[3] * inv;
            o4[0] = a;
        }
    }
}

// ---------------------------------------------------------------------------
extern "C" void kernel_launch(void* const* d_in, const int* in_sizes, int n_in,
                              void* d_out, int out_size)
{
    const float* x  = (const float*)d_in[0];
    const void*  ei = d_in[1];
    const float *Wl[6], *bl[6], *Wr[6];
    for (int i = 0; i < 6; i++) {
        Wl[i] = (const float*)d_in[2 + 3 * i];
        bl[i] = (const float*)d_in[3 + 3 * i];
        Wr[i] = (const float*)d_in[4 + 3 * i];
    }
    float* out = (float*)d_out;
    const int n = NN, e = EE;

    __half* pp = nullptr;
    float *ph0 = nullptr, *ph1 = nullptr;
    cudaGetSymbolAddress((void**)&pp,  g_p);
    cudaGetSymbolAddress((void**)&ph0, g_h0);
    cudaGetSymbolAddress((void**)&ph1, g_h1);

    // dynamic smem: sW + sh + sb
    // L0 (128,32,NJ=8,512): 64*32*16 + 128*128*4 + 32*4 = 98432
    // LS (32,32,NJ=8,256):  16*32*16 + 64*32*4  + 32*4 = 16512
    // L5 (32,16,NJ=4,256):  16*16*16 + 64*32*4  + 16*4 = 12352
    const int SM_L0 = 64 * 32 * 16 + 128 * 128 * 4 + 32 * 4;
    const int SM_LS = 16 * 32 * 16 + 64 * 32 * 4 + 32 * 4;
    const int SM_L5 = 16 * 16 * 16 + 64 * 32 * 4 + 16 * 4;
    cudaFuncSetAttribute(gemm_fused<128, 32, false, 8, 512, false>,
                         cudaFuncAttributeMaxDynamicSharedMemorySize, SM_L0);
    cudaFuncSetAttribute(gemm_fused<32, 32, true, 8, 256, false>,
                         cudaFuncAttributeMaxDynamicSharedMemorySize, SM_LS);
    cudaFuncSetAttribute(gemm_fused<32, 16, true, 4, 256, true>,
                         cudaFuncAttributeMaxDynamicSharedMemorySize, SM_L5);

    // nodes/block: L0: 128 ; small: 64 ; L5: 64
    const int G0  = (n + 127) / 128;
    const int GS  = (n + 63) / 64;
    const int G5  = (n + 63) / 64;
    const int blocksA = (n * 32 + 255) / 256;

    // ---- launch sequence (gemm0 placed 4th for ncu attribution) ----
    detect_kernel<<<1, 128>>>((const long long*)ei, n);
    zero_deg_kernel<<<(n + 255) / 256, 256>>>(n);
    prep_kernel<<<(e + 255) / 256, 256>>>(ei, e, n);
    gemm_fused<128, 32, false, 8, 512, false><<<G0, 512, SM_L0>>>(
        x, Wl[0], Wr[0], bl[0], pp, ph0, n);
    scan_blocks_kernel<<<SCAN_NB, 1024>>>(n);
    scan_bsums_kernel<<<1, 128>>>(SCAN_NB, n);
    finalize_offsets_kernel<<<SCAN_NB, 1024>>>(n);
    fill_kernel<<<(e + 255) / 256, 256>>>(ei, e, n);
    pad_tails_kernel<<<(n + 255) / 256, 256>>>(pp, n);

    aggregate_kernel<32><<<blocksA, 256>>>(pp, ph0, n);
    gemm_fused<32, 32, true, 8, 256, false><<<GS, 256, SM_LS>>>(
        ph0, Wl[1], Wr[1], bl[1], pp, ph1, n);
    aggregate_kernel<32><<<blocksA, 256>>>(pp, ph1, n);
    gemm_fused<32, 32, true, 8, 256, false><<<GS, 256, SM_LS>>>(
        ph1, Wl[2], Wr[2], bl[2], pp, ph0, n);
    aggregate_kernel<32><<<blocksA, 256>>>(pp, ph0, n);
    gemm_fused<32, 32, true, 8, 256, false><<<GS, 256, SM_LS>>>(
        ph0, Wl[3], Wr[3], bl[3], pp, ph1, n);
    aggregate_kernel<32><<<blocksA, 256>>>(pp, ph1, n);
    gemm_fused<32, 32, true, 8, 256, false><<<GS, 256, SM_LS>>>(
        ph1, Wl[4], Wr[4], bl[4], pp, ph0, n);
    aggregate_kernel<32><<<blocksA, 256>>>(pp, ph0, n);
    gemm_fused<32, 16, true, 4, 256, true><<<G5, 256, SM_L5>>>(
        ph0, Wl[5], Wr[5], bl[5], pp, out, n);
    aggregate_kernel<16><<<blocksA, 256>>>(pp, out, n);
}